// round 16
// baseline (speedup 1.0000x reference)
#include <cuda_runtime.h>
#include <cuda_bf16.h>
#include <mma.h>
#include <cstdint>

using namespace nvcuda;

#define C_EMBD 1024
#define NHEAD  16
#define HD     64
#define BATCH  4
#define SEQ    2048
#define M_TOT  8192
#define N_QKV  3072
#define KDIM   1024

// int8 hi/lo quantized operands for the qkv GEMM
__device__ __align__(16) int8_t g_xqh[M_TOT * KDIM],  g_xql[M_TOT * KDIM];
__device__ __align__(16) int8_t g_waqh[KDIM * N_QKV], g_waql[KDIM * N_QKV];  // [K][N]
// bf16 hi/lo for proj GEMM
__device__ __align__(16) __nv_bfloat16 g_wph[KDIM * C_EMBD], g_wpl[KDIM * C_EMBD];
__device__ __align__(16) __nv_bfloat16 g_yh[M_TOT * KDIM],   g_yl[M_TOT * KDIM];
#define QKV_ELEMS (BATCH * NHEAD * SEQ * HD)
__device__ __align__(16) __nv_bfloat16 g_qh[QKV_ELEMS], g_ql[QKV_ELEMS];
__device__ __align__(16) __nv_bfloat16 g_kh[QKV_ELEMS], g_kl[QKV_ELEMS];
__device__ __align__(16) __nv_bfloat16 g_vh[QKV_ELEMS], g_vl[QKV_ELEMS];

#define BND_X 6.0f
#define BND_W 0.12f
#define QMAX  32512.0f
#define SCALE_QKV ((BND_X / QMAX) * (BND_W / QMAX))

// ---------------------------------------------------------------------------
__device__ __forceinline__ uint32_t smem_u32(const void* p) {
    uint32_t a;
    asm("{ .reg .u64 t; cvta.to.shared.u64 t, %1; cvt.u32.u64 %0, t; }" : "=r"(a) : "l"(p));
    return a;
}
__device__ __forceinline__ uint32_t pack2(float lo, float hi) {
    uint32_t r;
    asm("cvt.rn.bf16x2.f32 %0, %1, %2;" : "=r"(r) : "f"(hi), "f"(lo));
    return r;
}
__device__ __forceinline__ void split2(float f0, float f1, uint32_t& hi, uint32_t& lo) {
    hi = pack2(f0, f1);
    float h0 = __uint_as_float(hi << 16);
    float h1 = __uint_as_float(hi & 0xffff0000u);
    lo = pack2(f0 - h0, f1 - h1);
}
#define CP16(dst_u32, src_ptr) \
    asm volatile("cp.async.cg.shared.global [%0], [%1], 16;" :: "r"(dst_u32), "l"(src_ptr))
#define CP_COMMIT() asm volatile("cp.async.commit_group;" ::: "memory")

// ---------------------------------------------------------------------------
// fp32 -> int16 fixed point as int8 hi/lo
// ---------------------------------------------------------------------------
__global__ __launch_bounds__(256) void cvt_q16(const float* __restrict__ src,
                                               int8_t* __restrict__ dh,
                                               int8_t* __restrict__ dl,
                                               float inv_s, int n4) {
    int i = blockIdx.x * 256 + threadIdx.x;
    if (i >= n4) return;
    float4 v = ((const float4*)src)[i];
    float f[4] = {v.x, v.y, v.z, v.w};
    int8_t h[4], l[4];
    #pragma unroll
    for (int e = 0; e < 4; e++) {
        float t = rintf(f[e] * inv_s);
        t = fminf(fmaxf(t, -QMAX), QMAX);
        int it = (int)t;
        int ih = (int)floorf(t * 0.00390625f + 0.5f);
        int il = it - (ih << 8);
        h[e] = (int8_t)ih;
        l[e] = (int8_t)il;
    }
    ((char4*)dh)[i] = make_char4(h[0], h[1], h[2], h[3]);
    ((char4*)dl)[i] = make_char4(l[0], l[1], l[2], l[3]);
}

// fp32 -> bf16 hi/lo (proj weights)
__global__ __launch_bounds__(256) void cvt_split(const float* __restrict__ src,
                                                 __nv_bfloat16* __restrict__ dh,
                                                 __nv_bfloat16* __restrict__ dl, int n4) {
    int i = blockIdx.x * 256 + threadIdx.x;
    if (i >= n4) return;
    float4 v = ((const float4*)src)[i];
    uint32_t h0, l0, h1, l1;
    split2(v.x, v.y, h0, l0);
    split2(v.z, v.w, h1, l1);
    ((uint2*)dh)[i] = make_uint2(h0, h1);
    ((uint2*)dl)[i] = make_uint2(l0, l1);
}

// ---------------------------------------------------------------------------
// int8 IMMA qkv GEMM: exact 16-bit fixed-point via 4 terms / 3 s32 acc sets.
// Block 64m x 64n, 256 threads = 8 warps (2m x 4n), warp tile 32x16, BK=32,
// 2-stage cp.async, 2 CTAs/SM. Epilogue: fp32 reconstruct + bias ->
// bf16 hi/lo scatter into g_{q,k,v}{h,l}.
// ---------------------------------------------------------------------------
#define I8_A_B 3072           // 64 rows x 48
#define I8_B_B 2560           // 32 rows x 80
#define I8_AH 0
#define I8_AL I8_A_B
#define I8_BH (2 * I8_A_B)
#define I8_BL (2 * I8_A_B + I8_B_B)
#define I8_STG (2 * I8_A_B + 2 * I8_B_B)   // 11264
#define I8_SMEM (2 * I8_STG)               // 22528
#define STG_LD 20

__global__ __launch_bounds__(256, 2) void gemm_qkv_i8(const float* __restrict__ bias) {
    extern __shared__ char dyn[];
    __shared__ __align__(16) int istage[8][16 * STG_LD];

    const int bm = blockIdx.y * 64;
    const int bn = blockIdx.x * 64;
    const int tid = threadIdx.x;
    const int wid = tid >> 5;
    const int lane = tid & 31;
    const int wm = (wid >> 2) * 32;
    const int wn = (wid & 3) * 16;

    const uint32_t dynb = smem_u32(dyn);
    const int tq = tid & 127;
    const bool hiSide = (tid < 128);

    auto issue = [&](int t) {
        const int k0 = t * 32;
        const uint32_t sb = dynb + (t & 1) * I8_STG;
        {   // A: 64 rows x 2 segs per matrix
            int row = tq >> 1, seg = tq & 1;
            const int8_t* src = (hiSide ? g_xqh : g_xql) + (size_t)(bm + row) * KDIM + k0 + seg * 16;
            CP16(sb + (hiSide ? I8_AH : I8_AL) + row * 48 + seg * 16, src);
        }
        {   // B: 32 rows x 4 segs per matrix
            int row = tq >> 2, seg = tq & 3;
            const int8_t* src = (hiSide ? g_waqh : g_waql) + (size_t)(k0 + row) * N_QKV + bn + seg * 16;
            CP16(sb + (hiSide ? I8_BH : I8_BL) + row * 80 + seg * 16, src);
        }
        CP_COMMIT();
    };

    issue(0);

    wmma::fragment<wmma::accumulator, 16, 16, 16, int> acc1[2], acc2[2], acc3[2];
    #pragma unroll
    for (int i = 0; i < 2; i++) {
        wmma::fill_fragment(acc1[i], 0);
        wmma::fill_fragment(acc2[i], 0);
        wmma::fill_fragment(acc3[i], 0);
    }

    const int nt = KDIM / 32;
    for (int t = 0; t < nt; t++) {
        if (t + 1 < nt) {
            issue(t + 1);
            asm volatile("cp.async.wait_group 1;" ::: "memory");
        } else {
            asm volatile("cp.async.wait_group 0;" ::: "memory");
        }
        __syncthreads();

        const char* sb = dyn + (t & 1) * I8_STG;
        const signed char* sAH = (const signed char*)(sb + I8_AH);
        const signed char* sAL = (const signed char*)(sb + I8_AL);
        const signed char* sBH = (const signed char*)(sb + I8_BH);
        const signed char* sBL = (const signed char*)(sb + I8_BL);

        #pragma unroll
        for (int kk = 0; kk < 32; kk += 16) {
            wmma::fragment<wmma::matrix_a, 16, 16, 16, signed char, wmma::row_major> aH[2], aL[2];
            wmma::fragment<wmma::matrix_b, 16, 16, 16, signed char, wmma::row_major> bH, bL;
            #pragma unroll
            for (int i = 0; i < 2; i++) {
                wmma::load_matrix_sync(aH[i], &sAH[(wm + i * 16) * 48 + kk], 48);
                wmma::load_matrix_sync(aL[i], &sAL[(wm + i * 16) * 48 + kk], 48);
            }
            wmma::load_matrix_sync(bH, &sBH[kk * 80 + wn], 80);
            wmma::load_matrix_sync(bL, &sBL[kk * 80 + wn], 80);
            #pragma unroll
            for (int i = 0; i < 2; i++) {
                wmma::mma_sync(acc1[i], aH[i], bH, acc1[i]);
                wmma::mma_sync(acc2[i], aH[i], bL, acc2[i]);
                wmma::mma_sync(acc2[i], aL[i], bH, acc2[i]);
                wmma::mma_sync(acc3[i], aL[i], bL, acc3[i]);
            }
        }
        __syncthreads();
    }

    // Epilogue: reconstruct fp32, add bias, split bf16 hi/lo, scatter.
    const int gn0 = bn + wn;
    const int which = gn0 >> 10;
    const int head = (gn0 >> 6) & 15;
    const int d0 = gn0 & 63;
    __nv_bfloat16 *dh, *dl;
    if (which == 0)      { dh = g_qh; dl = g_ql; }
    else if (which == 1) { dh = g_kh; dl = g_kl; }
    else                 { dh = g_vh; dl = g_vl; }

    #pragma unroll
    for (int i = 0; i < 2; i++) {
        int v1[8], v2[8], v3[8];
        wmma::store_matrix_sync(istage[wid], acc1[i], STG_LD, wmma::mem_row_major);
        __syncwarp();
        #pragma unroll
        for (int e = 0; e < 4; e++) {
            int pidx = lane * 4 + e, r = pidx >> 3, cp = pidx & 7;
            v1[2 * e] = istage[wid][r * STG_LD + 2 * cp];
            v1[2 * e + 1] = istage[wid][r * STG_LD + 2 * cp + 1];
        }
        __syncwarp();
        wmma::store_matrix_sync(istage[wid], acc2[i], STG_LD, wmma::mem_row_major);
        __syncwarp();
        #pragma unroll
        for (int e = 0; e < 4; e++) {
            int pidx = lane * 4 + e, r = pidx >> 3, cp = pidx & 7;
            v2[2 * e] = istage[wid][r * STG_LD + 2 * cp];
            v2[2 * e + 1] = istage[wid][r * STG_LD + 2 * cp + 1];
        }
        __syncwarp();
        wmma::store_matrix_sync(istage[wid], acc3[i], STG_LD, wmma::mem_row_major);
        __syncwarp();
        #pragma unroll
        for (int e = 0; e < 4; e++) {
            int pidx = lane * 4 + e, r = pidx >> 3, cp = pidx & 7;
            v3[2 * e] = istage[wid][r * STG_LD + 2 * cp];
            v3[2 * e + 1] = istage[wid][r * STG_LD + 2 * cp + 1];
        }
        __syncwarp();

        int m0 = bm + wm + i * 16;
        #pragma unroll
        for (int e = 0; e < 4; e++) {
            int pidx = lane * 4 + e, r = pidx >> 3, cp = pidx & 7;
            float f0 = fmaf(65536.f, (float)v1[2 * e],
                       fmaf(256.f, (float)v2[2 * e], (float)v3[2 * e])) * SCALE_QKV
                       + bias[gn0 + 2 * cp];
            float f1 = fmaf(65536.f, (float)v1[2 * e + 1],
                       fmaf(256.f, (float)v2[2 * e + 1], (float)v3[2 * e + 1])) * SCALE_QKV
                       + bias[gn0 + 2 * cp + 1];
            uint32_t h, l;
            split2(f0, f1, h, l);
            int m = m0 + r;
            int b = m >> 11, tt = m & 2047;
            size_t off = (((size_t)(b * NHEAD + head) * SEQ + tt) * HD + d0 + 2 * cp) >> 1;
            ((uint32_t*)dh)[off] = h;
            ((uint32_t*)dl)[off] = l;
        }
    }
}

// ---------------------------------------------------------------------------
// bf16 hi/lo 3-term proj GEMM (round-10 proven): out = y @ W_proj + b_proj.
// 256 threads = 8 warps (2m x 4n), warp 64x32, BK=32, 2-stage, 2 CTAs/SM.
// ---------------------------------------------------------------------------
#define AS_LD 40
#define BS_LD 136
#define A_BYTES (128 * AS_LD * 2)
#define B_BYTES (32 * BS_LD * 2)
#define STG_BYTES (2 * A_BYTES + 2 * B_BYTES)
#define OFF_AH 0
#define OFF_AL A_BYTES
#define OFF_BH (2 * A_BYTES)
#define OFF_BL (2 * A_BYTES + B_BYTES)
#define GEMM_SMEM (2 * STG_BYTES)

__global__ __launch_bounds__(256, 2) void gemm_proj(float* __restrict__ out,
                                                    const float* __restrict__ bias) {
    extern __shared__ char dyn[];
    __shared__ float sbias[16 * 132];

    const int bm = blockIdx.y * 128;
    const int bn = blockIdx.x * 128;
    const int tid = threadIdx.x;
    const int wid = tid >> 5;
    const int wm = (wid >> 2) * 64;
    const int wn = (wid & 3) * 32;

    const uint32_t dynb = smem_u32(dyn);
    const int am  = tid >> 1;
    const int asg = tid & 1;
    const int bkr = tid >> 4;
    const int bsg = tid & 15;

    auto issue = [&](int t) {
        const int k0 = t * 32;
        const uint32_t sb = dynb + (t & 1) * STG_BYTES;
        #pragma unroll
        for (int i = 0; i < 2; i++) {
            int seg = asg * 2 + i;
            const __nv_bfloat16* sa = &g_yh[(size_t)(bm + am) * KDIM + k0 + seg * 8];
            const __nv_bfloat16* sl = &g_yl[(size_t)(bm + am) * KDIM + k0 + seg * 8];
            CP16(sb + OFF_AH + am * (AS_LD * 2) + seg * 16, sa);
            CP16(sb + OFF_AL + am * (AS_LD * 2) + seg * 16, sl);
            int kr = bkr + i * 16;
            const __nv_bfloat16* sbh = &g_wph[(size_t)(k0 + kr) * C_EMBD + bn + bsg * 8];
            const __nv_bfloat16* sbl = &g_wpl[(size_t)(k0 + kr) * C_EMBD + bn + bsg * 8];
            CP16(sb + OFF_BH + kr * (BS_LD * 2) + bsg * 16, sbh);
            CP16(sb + OFF_BL + kr * (BS_LD * 2) + bsg * 16, sbl);
        }
        CP_COMMIT();
    };

    {
        int br = tid >> 4, bc = (tid & 15) * 8;
        float4 b0 = *(const float4*)&bias[bn + bc];
        float4 b1 = *(const float4*)&bias[bn + bc + 4];
        *(float4*)&sbias[br * 132 + bc] = b0;
        *(float4*)&sbias[br * 132 + bc + 4] = b1;
    }

    issue(0);

    wmma::fragment<wmma::accumulator, 16, 16, 16, float> acc[4][2];
    __syncthreads();
    #pragma unroll
    for (int i = 0; i < 4; i++)
        #pragma unroll
        for (int j = 0; j < 2; j++)
            wmma::load_matrix_sync(acc[i][j], &sbias[wn + j * 16], 132, wmma::mem_row_major);

    const int nt = KDIM / 32;
    for (int t = 0; t < nt; t++) {
        if (t + 1 < nt) {
            issue(t + 1);
            asm volatile("cp.async.wait_group 1;" ::: "memory");
        } else {
            asm volatile("cp.async.wait_group 0;" ::: "memory");
        }
        __syncthreads();

        const char* sb = dyn + (t & 1) * STG_BYTES;
        const __nv_bfloat16* sAH = (const __nv_bfloat16*)(sb + OFF_AH);
        const __nv_bfloat16* sAL = (const __nv_bfloat16*)(sb + OFF_AL);
        const __nv_bfloat16* sBH = (const __nv_bfloat16*)(sb + OFF_BH);
        const __nv_bfloat16* sBL = (const __nv_bfloat16*)(sb + OFF_BL);

        #pragma unroll
        for (int kk = 0; kk < 32; kk += 16) {
            wmma::fragment<wmma::matrix_a, 16, 16, 16, __nv_bfloat16, wmma::row_major> aH[4], aL[4];
            wmma::fragment<wmma::matrix_b, 16, 16, 16, __nv_bfloat16, wmma::row_major> bH[2], bL[2];
            #pragma unroll
            for (int i = 0; i < 4; i++) {
                wmma::load_matrix_sync(aH[i], &sAH[(wm + i * 16) * AS_LD + kk], AS_LD);
                wmma::load_matrix_sync(aL[i], &sAL[(wm + i * 16) * AS_LD + kk], AS_LD);
            }
            #pragma unroll
            for (int j = 0; j < 2; j++) {
                wmma::load_matrix_sync(bH[j], &sBH[kk * BS_LD + wn + j * 16], BS_LD);
                wmma::load_matrix_sync(bL[j], &sBL[kk * BS_LD + wn + j * 16], BS_LD);
            }
            #pragma unroll
            for (int i = 0; i < 4; i++)
                #pragma unroll
                for (int j = 0; j < 2; j++) {
                    wmma::mma_sync(acc[i][j], aH[i], bH[j], acc[i][j]);
                    wmma::mma_sync(acc[i][j], aH[i], bL[j], acc[i][j]);
                    wmma::mma_sync(acc[i][j], aL[i], bH[j], acc[i][j]);
                }
        }
        __syncthreads();
    }

    #pragma unroll
    for (int i = 0; i < 4; i++)
        #pragma unroll
        for (int j = 0; j < 2; j++) {
            int m0 = bm + wm + i * 16;
            int gn0 = bn + wn + j * 16;
            wmma::store_matrix_sync(&out[(size_t)m0 * C_EMBD + gn0],
                                    acc[i][j], C_EMBD, wmma::mem_row_major);
        }
}

// ---------------------------------------------------------------------------
// Tensor-core flash attention (round-10 proven, 3-term, 2 CTAs/SM).
// ---------------------------------------------------------------------------
#define TIL 9216
#define AT_SP_OFF  (10 * TIL)
#define AT_L_OFF   (AT_SP_OFF + 18432)
#define ATTN_SMEM  (AT_L_OFF + 256)

__global__ __launch_bounds__(256, 2) void attn_tc() {
    extern __shared__ char dyn[];
    const int tid = threadIdx.x;
    const int w = tid >> 5;
    const int bh = blockIdx.y;
    const int qt = (int)(gridDim.x - 1 - blockIdx.x);
    const int q0 = qt * 64;
    const uint32_t dynb = smem_u32(dyn);

    float* Ssm = (float*)(dyn + AT_SP_OFF);
    __nv_bfloat16* sPh = (__nv_bfloat16*)(dyn + AT_SP_OFF);
    __nv_bfloat16* sPl = (__nv_bfloat16*)(dyn + AT_SP_OFF + TIL);
    float* l_sm = (float*)(dyn + AT_L_OFF);

    {
        const size_t gq = ((size_t)bh * SEQ + q0) * 64;
        const __nv_bfloat16* srcs[2] = { g_qh + gq, g_ql + gq };
        #pragma unroll
        for (int a = 0; a < 2; a++)
            #pragma unroll
            for (int c2 = 0; c2 < 2; c2++) {
                int c = tid * 2 + c2;
                int row = c >> 3, seg = c & 7;
                CP16(dynb + a * TIL + row * 144 + seg * 16, srcs[a] + row * 64 + seg * 8);
            }
        CP_COMMIT();
    }
    if (tid < 64) l_sm[tid] = 0.0f;

    auto issueKV = [&](int jt) {
        const int buf = jt & 1;
        const size_t gb = ((size_t)bh * SEQ + jt * 64) * 64;
        const __nv_bfloat16* srcs[4] = { g_kh + gb, g_kl + gb, g_vh + gb, g_vl + gb };
        #pragma unroll
        for (int a = 0; a < 4; a++)
            #pragma unroll
            for (int c2 = 0; c2 < 2; c2++) {
                int c = tid * 2 + c2;
                int row = c >> 3, seg = c & 7;
                CP16(dynb + (2 + buf * 4 + a) * TIL + row * 144 + seg * 16,
                     srcs[a] + row * 64 + seg * 8);
            }
        CP_COMMIT();
    };
    issueKV(0);

    const int mrow = (w >> 1) * 16;
    const int half = (w & 1) * 32;

    wmma::fragment<wmma::accumulator, 16, 16, 16, float> o[2];
    wmma::fill_fragment(o[0], 0.0f);
    wmma::fill_fragment(o[1], 0.0f);

    for (int jt = 0; jt <= qt; jt++) {
        if (jt < qt) {
            issueKV(jt + 1);
            asm volatile("cp.async.wait_group 1;" ::: "memory");
        } else {
            asm volatile("cp.async.wait_group 0;" ::: "memory");
        }
        __syncthreads();
        const int buf = jt & 1;
        const __nv_bfloat16* sKh = (const __nv_bfloat16*)(dyn + (2 + buf * 4 + 0) * TIL);
        const __nv_bfloat16* sKl = (const __nv_bfloat16*)(dyn + (2 + buf * 4 + 1) * TIL);
        const __nv_bfloat16* sVh = (const __nv_bfloat16*)(dyn + (2 + buf * 4 + 2) * TIL);
        const __nv_bfloat16* sVl = (const __nv_bfloat16*)(dyn + (2 + buf * 4 + 3) * TIL);
        const __nv_bfloat16* sQh = (const __nv_bfloat16*)(dyn);
        const __nv_bfloat16* sQl = (const __nv_bfloat16*)(dyn + TIL);

        wmma::fragment<wmma::accumulator, 16, 16, 16, float> sf[2];
        wmma::fill_fragment(sf[0], 0.0f);
        wmma::fill_fragment(sf[1], 0.0f);
        #pragma unroll
        for (int ks = 0; ks < 4; ks++) {
            wmma::fragment<wmma::matrix_a, 16, 16, 16, __nv_bfloat16, wmma::row_major> aH, aL;
            wmma::load_matrix_sync(aH, &sQh[mrow * 72 + ks * 16], 72);
            wmma::load_matrix_sync(aL, &sQl[mrow * 72 + ks * 16], 72);
            #pragma unroll
            for (int n = 0; n < 2; n++) {
                wmma::fragment<wmma::matrix_b, 16, 16, 16, __nv_bfloat16, wmma::col_major> bH, bL;
                wmma::load_matrix_sync(bH, &sKh[(half + n * 16) * 72 + ks * 16], 72);
                wmma::load_matrix_sync(bL, &sKl[(half + n * 16) * 72 + ks * 16], 72);
                wmma::mma_sync(sf[n], aH, bH, sf[n]);
                wmma::mma_sync(sf[n], aH, bL, sf[n]);
                wmma::mma_sync(sf[n], aL, bH, sf[n]);
            }
        }
        wmma::store_matrix_sync(&Ssm[mrow * 72 + half], sf[0], 72, wmma::mem_row_major);
        wmma::store_matrix_sync(&Ssm[mrow * 72 + half + 16], sf[1], 72, wmma::mem_row_major);
        __syncthreads();

        {
            const int r = tid >> 2, seg = tid & 3;
            const int qg = q0 + r;
            const bool diag = (jt == qt);
            float sv[16];
            #pragma unroll
            for (int e = 0; e < 16; e++) sv[e] = Ssm[r * 72 + seg * 16 + e];
            __syncthreads();

            float p[16];
            float sum = 0.0f;
            #pragma unroll
            for (int e = 0; e < 16; e++) {
                float pe = __expf(sv[e] * 0.125f);
                if (diag) {
                    int jg = jt * 64 + seg * 16 + e;
                    if (jg > qg) pe = 0.0f;
                }
                p[e] = pe;
                sum += pe;
            }
            sum += __shfl_xor_sync(0xffffffff, sum, 1);
            sum += __shfl_xor_sync(0xffffffff, sum, 2);
            if ((tid & 3) == 0) l_sm[r] += sum;

            uint32_t* ph32 = (uint32_t*)sPh;
            uint32_t* pl32 = (uint32_t*)sPl;
            #pragma unroll
            for (int e = 0; e < 8; e++) {
                uint32_t h, l;
                split2(p[2 * e], p[2 * e + 1], h, l);
                ph32[r * 36 + seg * 8 + e] = h;
                pl32[r * 36 + seg * 8 + e] = l;
            }
        }
        __syncthreads();

        #pragma unroll
        for (int ks = 0; ks < 4; ks++) {
            wmma::fragment<wmma::matrix_a, 16, 16, 16, __nv_bfloat16, wmma::row_major> aH, aL;
            wmma::load_matrix_sync(aH, &sPh[mrow * 72 + ks * 16], 72);
            wmma::load_matrix_sync(aL, &sPl[mrow * 72 + ks * 16], 72);
            #pragma unroll
            for (int n = 0; n < 2; n++) {
                wmma::fragment<wmma::matrix_b, 16, 16, 16, __nv_bfloat16, wmma::row_major> bH, bL;
                wmma::load_matrix_sync(bH, &sVh[(ks * 16) * 72 + half + n * 16], 72);
                wmma::load_matrix_sync(bL, &sVl[(ks * 16) * 72 + half + n * 16], 72);
                wmma::mma_sync(o[n], aH, bH, o[n]);
                wmma::mma_sync(o[n], aH, bL, o[n]);
                wmma::mma_sync(o[n], aL, bH, o[n]);
            }
        }
        __syncthreads();
    }

    wmma::store_matrix_sync(&Ssm[mrow * 72 + half], o[0], 72, wmma::mem_row_major);
    wmma::store_matrix_sync(&Ssm[mrow * 72 + half + 16], o[1], 72, wmma::mem_row_major);
    __syncthreads();
    {
        const int r = tid >> 2, seg = tid & 3;
        const float inv = 1.0f / l_sm[r];
        const int b = bh >> 4, h = bh & 15;
        const size_t base = ((size_t)(b * SEQ) + q0 + r) * C_EMBD + h * 64;
        uint32_t* yh32 = (uint32_t*)g_yh;
        uint32_t* yl32 = (uint32_t*)g_yl;
        #pragma unroll
        for (int e = 0; e < 8; e++) {
            int c = seg * 16 + 2 * e;
            float o0 = Ssm[r * 72 + c] * inv;
            float o1 = Ssm[r * 72 + c + 1] * inv;
            uint32_t h2, l2;
            split2(o0, o1, h2, l2);
            yh32[(base + c) >> 1] = h2;
            yl32[(base + c) >> 1] = l2;
        }
    }
}

// ---------------------------------------------------------------------------
extern "C" void kernel_launch(void* const* d_in, const int* in_sizes, int n_in,
                              void* d_out, int out_size) {
    const float* x      = (const float*)d_in[0];
    const float* W_attn = (const float*)d_in[1];
    const float* b_attn = (const float*)d_in[2];
    const float* W_proj = (const float*)d_in[3];
    const float* b_proj = (const float*)d_in[4];
    float* out = (float*)d_out;

    cudaFuncSetAttribute(gemm_qkv_i8, cudaFuncAttributeMaxDynamicSharedMemorySize, I8_SMEM);
    cudaFuncSetAttribute(gemm_proj, cudaFuncAttributeMaxDynamicSharedMemorySize, GEMM_SMEM);
    cudaFuncSetAttribute(attn_tc, cudaFuncAttributeMaxDynamicSharedMemorySize, ATTN_SMEM);

    int8_t *xqh, *xql, *waqh, *waql;
    __nv_bfloat16 *wph, *wpl;
    cudaGetSymbolAddress((void**)&xqh,  g_xqh);
    cudaGetSymbolAddress((void**)&xql,  g_xql);
    cudaGetSymbolAddress((void**)&waqh, g_waqh);
    cudaGetSymbolAddress((void**)&waql, g_waql);
    cudaGetSymbolAddress((void**)&wph,  g_wph);
    cudaGetSymbolAddress((void**)&wpl,  g_wpl);

    cvt_q16<<<M_TOT * KDIM / 4 / 256, 256>>>(x, xqh, xql, QMAX / BND_X, M_TOT * KDIM / 4);
    cvt_q16<<<KDIM * N_QKV / 4 / 256, 256>>>(W_attn, waqh, waql, QMAX / BND_W, KDIM * N_QKV / 4);
    cvt_split<<<KDIM * C_EMBD / 4 / 256, 256>>>(W_proj, wph, wpl, KDIM * C_EMBD / 4);

    gemm_qkv_i8<<<dim3(N_QKV / 64, M_TOT / 64), 256, I8_SMEM>>>(b_attn);
    attn_tc<<<dim3(SEQ / 64, BATCH * NHEAD), 256, ATTN_SMEM>>>();
    gemm_proj<<<dim3(C_EMBD / 128, M_TOT / 128), 256, GEMM_SMEM>>>(out, b_proj);
}

// round 17
// speedup vs baseline: 2.6683x; 2.6683x over previous
#include <cuda_runtime.h>
#include <cuda_bf16.h>
#include <mma.h>
#include <cstdint>

using namespace nvcuda;

#define C_EMBD 1024
#define NHEAD  16
#define HD     64
#define BATCH  4
#define SEQ    2048
#define M_TOT  8192
#define N_QKV  3072
#define KDIM   1024

// bf16 hi/lo scratch
__device__ __align__(16) __nv_bfloat16 g_xh[M_TOT * KDIM],   g_xl[M_TOT * KDIM];
__device__ __align__(16) __nv_bfloat16 g_wah[KDIM * N_QKV],  g_wal[KDIM * N_QKV];
__device__ __align__(16) __nv_bfloat16 g_wph[KDIM * C_EMBD], g_wpl[KDIM * C_EMBD];
__device__ __align__(16) __nv_bfloat16 g_yh[M_TOT * KDIM],   g_yl[M_TOT * KDIM];
#define QKV_ELEMS (BATCH * NHEAD * SEQ * HD)
__device__ __align__(16) __nv_bfloat16 g_qh[QKV_ELEMS], g_ql[QKV_ELEMS];
__device__ __align__(16) __nv_bfloat16 g_kh[QKV_ELEMS], g_kl[QKV_ELEMS];
__device__ __align__(16) __nv_bfloat16 g_vh[QKV_ELEMS], g_vl[QKV_ELEMS];

// ---------------------------------------------------------------------------
__device__ __forceinline__ uint32_t smem_u32(const void* p) {
    uint32_t a;
    asm("{ .reg .u64 t; cvta.to.shared.u64 t, %1; cvt.u32.u64 %0, t; }" : "=r"(a) : "l"(p));
    return a;
}
__device__ __forceinline__ uint32_t pack2(float lo, float hi) {
    uint32_t r;
    asm("cvt.rn.bf16x2.f32 %0, %1, %2;" : "=r"(r) : "f"(hi), "f"(lo));
    return r;
}
__device__ __forceinline__ void split2(float f0, float f1, uint32_t& hi, uint32_t& lo) {
    hi = pack2(f0, f1);
    float h0 = __uint_as_float(hi << 16);
    float h1 = __uint_as_float(hi & 0xffff0000u);
    lo = pack2(f0 - h0, f1 - h1);
}
#define CP16(dst_u32, src_ptr) \
    asm volatile("cp.async.cg.shared.global [%0], [%1], 16;" :: "r"(dst_u32), "l"(src_ptr))
#define CP_COMMIT() asm volatile("cp.async.commit_group;" ::: "memory")

// ---------------------------------------------------------------------------
// Fused conversion: x, W_attn, W_proj -> bf16 hi/lo in one launch.
// ---------------------------------------------------------------------------
#define N4_X  (M_TOT * KDIM / 4)
#define N4_WA (KDIM * N_QKV / 4)
#define N4_WP (KDIM * C_EMBD / 4)
__global__ __launch_bounds__(256) void cvt_all(const float* __restrict__ x,
                                               const float* __restrict__ wa,
                                               const float* __restrict__ wp) {
    int i = blockIdx.x * 256 + threadIdx.x;
    const float4* s4;
    uint2 *dh, *dl;
    int j;
    if (i < N4_X) {
        j = i; s4 = (const float4*)x;
        dh = (uint2*)g_xh; dl = (uint2*)g_xl;
    } else if (i < N4_X + N4_WA) {
        j = i - N4_X; s4 = (const float4*)wa;
        dh = (uint2*)g_wah; dl = (uint2*)g_wal;
    } else if (i < N4_X + N4_WA + N4_WP) {
        j = i - N4_X - N4_WA; s4 = (const float4*)wp;
        dh = (uint2*)g_wph; dl = (uint2*)g_wpl;
    } else return;
    float4 v = s4[j];
    uint32_t h0, l0, h1, l1;
    split2(v.x, v.y, h0, l0);
    split2(v.z, v.w, h1, l1);
    dh[j] = make_uint2(h0, h1);
    dl[j] = make_uint2(l0, l1);
}

// ---------------------------------------------------------------------------
// wmma bf16 hi/lo 3-term GEMM (round-10 config), single-sync pipeline:
// per k-step: wait_group 0 -> __syncthreads -> issue(t+1) -> compute.
// The barrier proves all warps finished iter t-1, so overwriting buffer
// (t+1)&1 == (t-1)&1 after it is safe; trailing sync removed.
// ---------------------------------------------------------------------------
#define AS_LD 40
#define BS_LD 136
#define A_BYTES (128 * AS_LD * 2)
#define B_BYTES (32 * BS_LD * 2)
#define STG_BYTES (2 * A_BYTES + 2 * B_BYTES)   // 37888
#define OFF_AH 0
#define OFF_AL A_BYTES
#define OFF_BH (2 * A_BYTES)
#define OFF_BL (2 * A_BYTES + B_BYTES)
#define GEMM_SMEM (2 * STG_BYTES)               // 75776 -> 2 CTAs/SM
#define STG_LD 20

template <int EPI>
__global__ __launch_bounds__(256, 2) void gemm_wmma2(float* __restrict__ out,
                                                     const float* __restrict__ bias) {
    constexpr int N = (EPI == 0) ? N_QKV : C_EMBD;
    extern __shared__ char dyn[];
    __shared__ float sbias[16 * 132];
    __shared__ float stage[8][16 * STG_LD];

    const int bm = blockIdx.y * 128;
    const int bn = blockIdx.x * 128;
    const int tid = threadIdx.x;
    const int wid = tid >> 5;
    const int lane = tid & 31;
    const int wm = (wid >> 2) * 64;
    const int wn = (wid & 3) * 32;

    const __nv_bfloat16* Ah = (EPI == 0) ? g_xh : g_yh;
    const __nv_bfloat16* Al = (EPI == 0) ? g_xl : g_yl;
    const __nv_bfloat16* Bh = (EPI == 0) ? g_wah : g_wph;
    const __nv_bfloat16* Bl = (EPI == 0) ? g_wal : g_wpl;

    const uint32_t dynb = smem_u32(dyn);
    const int am  = tid >> 1;
    const int asg = tid & 1;
    const int bkr = tid >> 4;
    const int bsg = tid & 15;

    auto issue = [&](int t) {
        const int k0 = t * 32;
        const uint32_t sb = dynb + (t & 1) * STG_BYTES;
        #pragma unroll
        for (int i = 0; i < 2; i++) {
            int seg = asg * 2 + i;
            const __nv_bfloat16* sa = &Ah[(size_t)(bm + am) * KDIM + k0 + seg * 8];
            const __nv_bfloat16* sl = &Al[(size_t)(bm + am) * KDIM + k0 + seg * 8];
            CP16(sb + OFF_AH + am * (AS_LD * 2) + seg * 16, sa);
            CP16(sb + OFF_AL + am * (AS_LD * 2) + seg * 16, sl);
            int kr = bkr + i * 16;
            const __nv_bfloat16* sbh = &Bh[(size_t)(k0 + kr) * N + bn + bsg * 8];
            const __nv_bfloat16* sbl = &Bl[(size_t)(k0 + kr) * N + bn + bsg * 8];
            CP16(sb + OFF_BH + kr * (BS_LD * 2) + bsg * 16, sbh);
            CP16(sb + OFF_BL + kr * (BS_LD * 2) + bsg * 16, sbl);
        }
        CP_COMMIT();
    };

    {
        int br = tid >> 4, bc = (tid & 15) * 8;
        float4 b0 = *(const float4*)&bias[bn + bc];
        float4 b1 = *(const float4*)&bias[bn + bc + 4];
        *(float4*)&sbias[br * 132 + bc] = b0;
        *(float4*)&sbias[br * 132 + bc + 4] = b1;
    }

    issue(0);

    wmma::fragment<wmma::accumulator, 16, 16, 16, float> acc[4][2];
    __syncthreads();   // sbias visible
    #pragma unroll
    for (int i = 0; i < 4; i++)
        #pragma unroll
        for (int j = 0; j < 2; j++)
            wmma::load_matrix_sync(acc[i][j], &sbias[wn + j * 16], 132, wmma::mem_row_major);

    const int nt = KDIM / 32;
    for (int t = 0; t < nt; t++) {
        asm volatile("cp.async.wait_group 0;" ::: "memory");
        __syncthreads();
        if (t + 1 < nt) issue(t + 1);

        const char* sb = dyn + (t & 1) * STG_BYTES;
        const __nv_bfloat16* sAH = (const __nv_bfloat16*)(sb + OFF_AH);
        const __nv_bfloat16* sAL = (const __nv_bfloat16*)(sb + OFF_AL);
        const __nv_bfloat16* sBH = (const __nv_bfloat16*)(sb + OFF_BH);
        const __nv_bfloat16* sBL = (const __nv_bfloat16*)(sb + OFF_BL);

        #pragma unroll
        for (int kk = 0; kk < 32; kk += 16) {
            wmma::fragment<wmma::matrix_a, 16, 16, 16, __nv_bfloat16, wmma::row_major> aH[4], aL[4];
            wmma::fragment<wmma::matrix_b, 16, 16, 16, __nv_bfloat16, wmma::row_major> bH[2], bL[2];
            #pragma unroll
            for (int i = 0; i < 4; i++) {
                wmma::load_matrix_sync(aH[i], &sAH[(wm + i * 16) * AS_LD + kk], AS_LD);
                wmma::load_matrix_sync(aL[i], &sAL[(wm + i * 16) * AS_LD + kk], AS_LD);
            }
            #pragma unroll
            for (int j = 0; j < 2; j++) {
                wmma::load_matrix_sync(bH[j], &sBH[kk * BS_LD + wn + j * 16], BS_LD);
                wmma::load_matrix_sync(bL[j], &sBL[kk * BS_LD + wn + j * 16], BS_LD);
            }
            #pragma unroll
            for (int i = 0; i < 4; i++)
                #pragma unroll
                for (int j = 0; j < 2; j++) {
                    wmma::mma_sync(acc[i][j], aH[i], bH[j], acc[i][j]);
                    wmma::mma_sync(acc[i][j], aH[i], bL[j], acc[i][j]);
                    wmma::mma_sync(acc[i][j], aL[i], bH[j], acc[i][j]);
                }
        }
    }

    #pragma unroll
    for (int i = 0; i < 4; i++) {
        #pragma unroll
        for (int j = 0; j < 2; j++) {
            int m0 = bm + wm + i * 16;
            int gn0 = bn + wn + j * 16;
            if (EPI == 0) {
                wmma::store_matrix_sync(stage[wid], acc[i][j], STG_LD, wmma::mem_row_major);
                __syncwarp();
                int which = gn0 >> 10;
                int head = (gn0 >> 6) & 15;
                int d0 = gn0 & 63;
                __nv_bfloat16* dh = (which == 0) ? g_qh : (which == 1) ? g_kh : g_vh;
                __nv_bfloat16* dl = (which == 0) ? g_ql : (which == 1) ? g_kl : g_vl;
                #pragma unroll
                for (int e = 0; e < 4; e++) {
                    int pidx = lane * 4 + e;
                    int r = pidx >> 3, cp = pidx & 7;
                    float f0 = stage[wid][r * STG_LD + 2 * cp];
                    float f1 = stage[wid][r * STG_LD + 2 * cp + 1];
                    uint32_t h, l;
                    split2(f0, f1, h, l);
                    int m = m0 + r;
                    int b = m >> 11, tt = m & 2047;
                    size_t off = (((size_t)(b * NHEAD + head) * SEQ + tt) * HD + d0 + 2 * cp) >> 1;
                    ((uint32_t*)dh)[off] = h;
                    ((uint32_t*)dl)[off] = l;
                }
                __syncwarp();
            } else {
                wmma::store_matrix_sync(&out[(size_t)m0 * C_EMBD + gn0],
                                        acc[i][j], C_EMBD, wmma::mem_row_major);
            }
        }
    }
}

// ---------------------------------------------------------------------------
// Tensor-core flash attention (round-10 structure), single-sync KV pipeline:
// per jt: wait_group 0 -> sync -> issueKV(jt+1) -> S mma -> ... -> PV mma
// (no trailing sync; next iter's first barrier subsumes it; one barrier added
// before the epilogue Ssm overwrite).
// ---------------------------------------------------------------------------
#define TIL 9216
#define AT_SP_OFF  (10 * TIL)
#define AT_L_OFF   (AT_SP_OFF + 18432)
#define ATTN_SMEM  (AT_L_OFF + 256)

__global__ __launch_bounds__(256, 2) void attn_tc() {
    extern __shared__ char dyn[];
    const int tid = threadIdx.x;
    const int w = tid >> 5;
    const int bh = blockIdx.y;
    const int qt = (int)(gridDim.x - 1 - blockIdx.x);
    const int q0 = qt * 64;
    const uint32_t dynb = smem_u32(dyn);

    float* Ssm = (float*)(dyn + AT_SP_OFF);
    __nv_bfloat16* sPh = (__nv_bfloat16*)(dyn + AT_SP_OFF);
    __nv_bfloat16* sPl = (__nv_bfloat16*)(dyn + AT_SP_OFF + TIL);
    float* l_sm = (float*)(dyn + AT_L_OFF);

    {
        const size_t gq = ((size_t)bh * SEQ + q0) * 64;
        const __nv_bfloat16* srcs[2] = { g_qh + gq, g_ql + gq };
        #pragma unroll
        for (int a = 0; a < 2; a++)
            #pragma unroll
            for (int c2 = 0; c2 < 2; c2++) {
                int c = tid * 2 + c2;
                int row = c >> 3, seg = c & 7;
                CP16(dynb + a * TIL + row * 144 + seg * 16, srcs[a] + row * 64 + seg * 8);
            }
        CP_COMMIT();
    }
    if (tid < 64) l_sm[tid] = 0.0f;

    auto issueKV = [&](int jt) {
        const int buf = jt & 1;
        const size_t gb = ((size_t)bh * SEQ + jt * 64) * 64;
        const __nv_bfloat16* srcs[4] = { g_kh + gb, g_kl + gb, g_vh + gb, g_vl + gb };
        #pragma unroll
        for (int a = 0; a < 4; a++)
            #pragma unroll
            for (int c2 = 0; c2 < 2; c2++) {
                int c = tid * 2 + c2;
                int row = c >> 3, seg = c & 7;
                CP16(dynb + (2 + buf * 4 + a) * TIL + row * 144 + seg * 16,
                     srcs[a] + row * 64 + seg * 8);
            }
        CP_COMMIT();
    };
    issueKV(0);

    const int mrow = (w >> 1) * 16;
    const int half = (w & 1) * 32;

    wmma::fragment<wmma::accumulator, 16, 16, 16, float> o[2];
    wmma::fill_fragment(o[0], 0.0f);
    wmma::fill_fragment(o[1], 0.0f);

    for (int jt = 0; jt <= qt; jt++) {
        asm volatile("cp.async.wait_group 0;" ::: "memory");
        __syncthreads();                  // KV[jt] visible; all warps done iter jt-1
        if (jt < qt) issueKV(jt + 1);     // writes other buffer; safe after barrier

        const int buf = jt & 1;
        const __nv_bfloat16* sKh = (const __nv_bfloat16*)(dyn + (2 + buf * 4 + 0) * TIL);
        const __nv_bfloat16* sKl = (const __nv_bfloat16*)(dyn + (2 + buf * 4 + 1) * TIL);
        const __nv_bfloat16* sVh = (const __nv_bfloat16*)(dyn + (2 + buf * 4 + 2) * TIL);
        const __nv_bfloat16* sVl = (const __nv_bfloat16*)(dyn + (2 + buf * 4 + 3) * TIL);
        const __nv_bfloat16* sQh = (const __nv_bfloat16*)(dyn);
        const __nv_bfloat16* sQl = (const __nv_bfloat16*)(dyn + TIL);

        wmma::fragment<wmma::accumulator, 16, 16, 16, float> sf[2];
        wmma::fill_fragment(sf[0], 0.0f);
        wmma::fill_fragment(sf[1], 0.0f);
        #pragma unroll
        for (int ks = 0; ks < 4; ks++) {
            wmma::fragment<wmma::matrix_a, 16, 16, 16, __nv_bfloat16, wmma::row_major> aH, aL;
            wmma::load_matrix_sync(aH, &sQh[mrow * 72 + ks * 16], 72);
            wmma::load_matrix_sync(aL, &sQl[mrow * 72 + ks * 16], 72);
            #pragma unroll
            for (int n = 0; n < 2; n++) {
                wmma::fragment<wmma::matrix_b, 16, 16, 16, __nv_bfloat16, wmma::col_major> bH, bL;
                wmma::load_matrix_sync(bH, &sKh[(half + n * 16) * 72 + ks * 16], 72);
                wmma::load_matrix_sync(bL, &sKl[(half + n * 16) * 72 + ks * 16], 72);
                wmma::mma_sync(sf[n], aH, bH, sf[n]);
                wmma::mma_sync(sf[n], aH, bL, sf[n]);
                wmma::mma_sync(sf[n], aL, bH, sf[n]);
            }
        }
        wmma::store_matrix_sync(&Ssm[mrow * 72 + half], sf[0], 72, wmma::mem_row_major);
        wmma::store_matrix_sync(&Ssm[mrow * 72 + half + 16], sf[1], 72, wmma::mem_row_major);
        __syncthreads();

        {
            const int r = tid >> 2, seg = tid & 3;
            const int qg = q0 + r;
            const bool diag = (jt == qt);
            float sv[16];
            #pragma unroll
            for (int e = 0; e < 16; e++) sv[e] = Ssm[r * 72 + seg * 16 + e];
            __syncthreads();   // S fully read before P overwrites (alias)

            float p[16];
            float sum = 0.0f;
            #pragma unroll
            for (int e = 0; e < 16; e++) {
                float pe = __expf(sv[e] * 0.125f);
                if (diag) {
                    int jg = jt * 64 + seg * 16 + e;
                    if (jg > qg) pe = 0.0f;
                }
                p[e] = pe;
                sum += pe;
            }
            sum += __shfl_xor_sync(0xffffffff, sum, 1);
            sum += __shfl_xor_sync(0xffffffff, sum, 2);
            if ((tid & 3) == 0) l_sm[r] += sum;

            uint32_t* ph32 = (uint32_t*)sPh;
            uint32_t* pl32 = (uint32_t*)sPl;
            #pragma unroll
            for (int e = 0; e < 8; e++) {
                uint32_t h, l;
                split2(p[2 * e], p[2 * e + 1], h, l);
                ph32[r * 36 + seg * 8 + e] = h;
                pl32[r * 36 + seg * 8 + e] = l;
            }
        }
        __syncthreads();

        #pragma unroll
        for (int ks = 0; ks < 4; ks++) {
            wmma::fragment<wmma::matrix_a, 16, 16, 16, __nv_bfloat16, wmma::row_major> aH, aL;
            wmma::load_matrix_sync(aH, &sPh[mrow * 72 + ks * 16], 72);
            wmma::load_matrix_sync(aL, &sPl[mrow * 72 + ks * 16], 72);
            #pragma unroll
            for (int n = 0; n < 2; n++) {
                wmma::fragment<wmma::matrix_b, 16, 16, 16, __nv_bfloat16, wmma::row_major> bH, bL;
                wmma::load_matrix_sync(bH, &sVh[(ks * 16) * 72 + half + n * 16], 72);
                wmma::load_matrix_sync(bL, &sVl[(ks * 16) * 72 + half + n * 16], 72);
                wmma::mma_sync(o[n], aH, bH, o[n]);
                wmma::mma_sync(o[n], aH, bL, o[n]);
                wmma::mma_sync(o[n], aL, bH, o[n]);
            }
        }
        // no trailing sync: next iteration's first barrier subsumes it
    }

    __syncthreads();   // all PV reads of P/Ssm done before epilogue overwrite
    wmma::store_matrix_sync(&Ssm[mrow * 72 + half], o[0], 72, wmma::mem_row_major);
    wmma::store_matrix_sync(&Ssm[mrow * 72 + half + 16], o[1], 72, wmma::mem_row_major);
    __syncthreads();
    {
        const int r = tid >> 2, seg = tid & 3;
        const float inv = 1.0f / l_sm[r];
        const int b = bh >> 4, h = bh & 15;
        const size_t base = ((size_t)(b * SEQ) + q0 + r) * C_EMBD + h * 64;
        uint32_t* yh32 = (uint32_t*)g_yh;
        uint32_t* yl32 = (uint32_t*)g_yl;
        #pragma unroll
        for (int e = 0; e < 8; e++) {
            int c = seg * 16 + 2 * e;
            float o0 = Ssm[r * 72 + c] * inv;
            float o1 = Ssm[r * 72 + c + 1] * inv;
            uint32_t h2, l2;
            split2(o0, o1, h2, l2);
            yh32[(base + c) >> 1] = h2;
            yl32[(base + c) >> 1] = l2;
        }
    }
}

// ---------------------------------------------------------------------------
extern "C" void kernel_launch(void* const* d_in, const int* in_sizes, int n_in,
                              void* d_out, int out_size) {
    const float* x      = (const float*)d_in[0];
    const float* W_attn = (const float*)d_in[1];
    const float* b_attn = (const float*)d_in[2];
    const float* W_proj = (const float*)d_in[3];
    const float* b_proj = (const float*)d_in[4];
    float* out = (float*)d_out;

    cudaFuncSetAttribute(gemm_wmma2<0>, cudaFuncAttributeMaxDynamicSharedMemorySize, GEMM_SMEM);
    cudaFuncSetAttribute(gemm_wmma2<1>, cudaFuncAttributeMaxDynamicSharedMemorySize, GEMM_SMEM);
    cudaFuncSetAttribute(attn_tc, cudaFuncAttributeMaxDynamicSharedMemorySize, ATTN_SMEM);

    const int n4_total = N4_X + N4_WA + N4_WP;
    cvt_all<<<(n4_total + 255) / 256, 256>>>(x, W_attn, W_proj);

    gemm_wmma2<0><<<dim3(N_QKV / 128, M_TOT / 128), 256, GEMM_SMEM>>>(nullptr, b_attn);
    attn_tc<<<dim3(SEQ / 64, BATCH * NHEAD), 256, ATTN_SMEM>>>();
    gemm_wmma2<1><<<dim3(C_EMBD / 128, M_TOT / 128), 256, GEMM_SMEM>>>(out, b_proj);
}